// round 16
// baseline (speedup 1.0000x reference)
#include <cuda_runtime.h>

// Shapes: x [8,16,4,8192,2] f32; psi_hat [24,16384,2]; phi_hat [1,16384,2];
// idx [32,2] int32 (sniffed, tolerates int64); out [8,32,4,8192,2] f32.
#define N_FFT    16384
#define T_LEN    8192
#define NT       1024
#define NSEQ     512
#define NGRID    148
// Bank-conflict-avoiding padded smem index: one extra float2 per 16.
#define P(i) ((i) + ((i) >> 4))
#define SMEM_F2    (N_FFT + N_FFT / 16)
#define SMEM_BYTES (SMEM_F2 * 8)             // 139264 bytes

__device__ __align__(16) float2 g_tw[N_FFT / 4];         // 32KB, L1-hot
__device__ __align__(16) float2 g_xhat[NSEQ * N_FFT];    // 64 MiB
__device__ __align__(16) float2 g_filtrev[26 * N_FFT];   // digit-reversed filters
__device__ int g_idx[64];        // normalized (jr, f) pairs
__device__ int g_live[NSEQ];     // compacted list of referenced fwd seqs
__device__ int g_nlive;
__device__ int g_ctr_fwd;        // persistent-CTA work counters (reset in prep)
__device__ int g_ctr_inv;

__device__ __forceinline__ float2 cmul(float2 a, float2 b) {
    return make_float2(fmaf(a.x, b.x, -a.y * b.y), fmaf(a.x, b.y, a.y * b.x));
}

// DIF butterfly, twiddles applied to outputs.
__device__ __forceinline__ void bfly4_dif_t(float2& x0, float2& x1, float2& x2,
                                            float2& x3, float2 w1, float2 w2, float2 w3) {
    float2 t0 = make_float2(x0.x + x2.x, x0.y + x2.y);
    float2 t1 = make_float2(x0.x - x2.x, x0.y - x2.y);
    float2 t2 = make_float2(x1.x + x3.x, x1.y + x3.y);
    float2 t3 = make_float2(x1.x - x3.x, x1.y - x3.y);
    x0 = make_float2(t0.x + t2.x, t0.y + t2.y);
    float2 y1 = make_float2(t1.x + t3.y, t1.y - t3.x);   // t1 - i*t3
    float2 y2 = make_float2(t0.x - t2.x, t0.y - t2.y);
    float2 y3 = make_float2(t1.x - t3.y, t1.y + t3.x);   // t1 + i*t3
    x1 = cmul(y1, w1);
    x2 = cmul(y2, w2);
    x3 = cmul(y3, w3);
}
__device__ __forceinline__ void bfly4_dif(float2& x0, float2& x1, float2& x2,
                                          float2& x3, float2 w1) {
    float2 w2 = cmul(w1, w1);
    bfly4_dif_t(x0, x1, x2, x3, w1, w2, cmul(w2, w1));
}
__device__ __forceinline__ void bfly4_dif_nw(float2& x0, float2& x1,
                                             float2& x2, float2& x3) {
    float2 t0 = make_float2(x0.x + x2.x, x0.y + x2.y);
    float2 t1 = make_float2(x0.x - x2.x, x0.y - x2.y);
    float2 t2 = make_float2(x1.x + x3.x, x1.y + x3.y);
    float2 t3 = make_float2(x1.x - x3.x, x1.y - x3.y);
    x0 = make_float2(t0.x + t2.x, t0.y + t2.y);
    x1 = make_float2(t1.x + t3.y, t1.y - t3.x);
    x2 = make_float2(t0.x - t2.x, t0.y - t2.y);
    x3 = make_float2(t1.x - t3.y, t1.y + t3.x);
}

// DIT butterfly, conjugated twiddles applied to inputs.
__device__ __forceinline__ void bfly4_dit_t(float2& x0, float2& x1, float2& x2,
                                            float2& x3, float2 w1, float2 w2, float2 w3) {
    float2 b1 = cmul(x1, w1);
    float2 b2 = cmul(x2, w2);
    float2 b3 = cmul(x3, w3);
    float2 t0 = make_float2(x0.x + b2.x, x0.y + b2.y);
    float2 t1 = make_float2(x0.x - b2.x, x0.y - b2.y);
    float2 t2 = make_float2(b1.x + b3.x, b1.y + b3.y);
    float2 t3 = make_float2(b1.x - b3.x, b1.y - b3.y);
    x0 = make_float2(t0.x + t2.x, t0.y + t2.y);
    x1 = make_float2(t1.x - t3.y, t1.y + t3.x);          // t1 + i*t3
    x2 = make_float2(t0.x - t2.x, t0.y - t2.y);
    x3 = make_float2(t1.x + t3.y, t1.y - t3.x);          // t1 - i*t3
}
__device__ __forceinline__ void bfly4_dit(float2& x0, float2& x1, float2& x2,
                                          float2& x3, float2 w1c) {
    float2 w2 = cmul(w1c, w1c);
    bfly4_dit_t(x0, x1, x2, x3, w1c, w2, cmul(w2, w1c));
}
__device__ __forceinline__ void bfly4_dit_nw(float2& x0, float2& x1,
                                             float2& x2, float2& x3) {
    float2 t0 = make_float2(x0.x + x2.x, x0.y + x2.y);
    float2 t1 = make_float2(x0.x - x2.x, x0.y - x2.y);
    float2 t2 = make_float2(x1.x + x3.x, x1.y + x3.y);
    float2 t3 = make_float2(x1.x - x3.x, x1.y - x3.y);
    x0 = make_float2(t0.x + t2.x, t0.y + t2.y);
    x1 = make_float2(t1.x - t3.y, t1.y + t3.x);
    x2 = make_float2(t0.x - t2.x, t0.y - t2.y);
    x3 = make_float2(t1.x + t3.y, t1.y - t3.x);
}

// Fused DIF stage pair (S, S+1), one 16-point unit per thread, smem->smem.
template <int S>
__device__ __forceinline__ void fwd_fused_phase(float2* sm, int v) {
    constexpr int l2 = 12 - 2 * S;
    constexpr int L  = 1 << l2;
    constexpr int L4 = L >> 2;
    int block = v >> (l2 - 2);
    int j0 = v & (L4 - 1);
    int base = (block << (l2 + 2)) + j0;
    float2 d[4][4];
#pragma unroll
    for (int m = 0; m < 4; m++)
#pragma unroll
        for (int q = 0; q < 4; q++)
            d[m][q] = sm[P(base + m * L4 + q * L)];
#pragma unroll
    for (int m = 0; m < 4; m++)
        bfly4_dif(d[m][0], d[m][1], d[m][2], d[m][3],
                  g_tw[(j0 + m * L4) << (2 * S)]);
    {
        float2 w1 = g_tw[j0 << (2 * S + 2)];
        float2 w2 = cmul(w1, w1);
        float2 w3 = cmul(w2, w1);
#pragma unroll
        for (int q = 0; q < 4; q++)
            bfly4_dif_t(d[0][q], d[1][q], d[2][q], d[3][q], w1, w2, w3);
    }
#pragma unroll
    for (int m = 0; m < 4; m++)
#pragma unroll
        for (int q = 0; q < 4; q++)
            sm[P(base + m * L4 + q * L)] = d[m][q];
    __syncthreads();
}

// Exact inverse: stage S+1 then S, conjugated twiddles.
template <int S>
__device__ __forceinline__ void inv_fused_phase(float2* sm, int v) {
    constexpr int l2 = 12 - 2 * S;
    constexpr int L  = 1 << l2;
    constexpr int L4 = L >> 2;
    int block = v >> (l2 - 2);
    int j0 = v & (L4 - 1);
    int base = (block << (l2 + 2)) + j0;
    float2 d[4][4];
#pragma unroll
    for (int m = 0; m < 4; m++)
#pragma unroll
        for (int q = 0; q < 4; q++)
            d[m][q] = sm[P(base + m * L4 + q * L)];
    {
        float2 w1 = g_tw[j0 << (2 * S + 2)];
        w1.y = -w1.y;
        float2 w2 = cmul(w1, w1);
        float2 w3 = cmul(w2, w1);
#pragma unroll
        for (int q = 0; q < 4; q++)
            bfly4_dit_t(d[0][q], d[1][q], d[2][q], d[3][q], w1, w2, w3);
    }
#pragma unroll
    for (int m = 0; m < 4; m++) {
        float2 w1 = g_tw[(j0 + m * L4) << (2 * S)];
        w1.y = -w1.y;
        bfly4_dit(d[m][0], d[m][1], d[m][2], d[m][3], w1);
    }
#pragma unroll
    for (int m = 0; m < 4; m++)
#pragma unroll
        for (int q = 0; q < 4; q++)
            sm[P(base + m * L4 + q * L)] = d[m][q];
    __syncthreads();
}

__device__ __forceinline__ int digitrev4(int v) {
    int r = 0;
#pragma unroll
    for (int i = 0; i < 7; i++) { r = (r << 2) | (v & 3); v >>= 2; }
    return r;
}

// Merged prep kernel, grid = 216 x 512.
//   blocks [0,208): filter row b>>3, src-chunk b&7. digitrev4 is an involution,
//     so iterate CONTIGUOUS sources (coalesced loads, no scoreboard stall) and
//     scatter the stores (fire-and-forget).
//   blocks [208,216): twiddle table chunk
//   block 0 also   : publish g_idx/g_live/g_nlive, reset work counters
__global__ void prep_kernel(const float* __restrict__ psi,
                            const float* __restrict__ phi,
                            const int* __restrict__ raw) {
    const int b   = blockIdx.x;
    const int tid = threadIdx.x;

    if (b >= 208) {                             // twiddle chunk
        int k = (b - 208) * 512 + tid;
        double s, c;
        sincospi(-2.0 * (double)k / (double)N_FFT, &s, &c);
        g_tw[k] = make_float2((float)c, (float)s);
        return;
    }

    __shared__ int s_idx[64];
    __shared__ int s_cnt[16];
    __shared__ unsigned s_fmask;
    if (tid < 32) {
        // sniff: int64 little-endian => all odd 32-bit words zero
        int odd = raw[2 * tid + 1];
        unsigned nz = __ballot_sync(0xffffffffu, odd != 0);
        int jr, f;
        if (nz) { jr = raw[2 * tid];     f = raw[2 * tid + 1]; }  // int32
        else    { jr = raw[4 * tid];     f = raw[4 * tid + 2]; }  // int64 low words
        s_idx[2 * tid]     = min(max(jr, 0), 15);
        s_idx[2 * tid + 1] = min(max(f, 0), 25);
    }
    __syncthreads();
    if (tid == 0) {
        int cnt[16];
        unsigned fm = 0;
        for (int j = 0; j < 16; j++) cnt[j] = 0;
        for (int cj = 0; cj < 32; cj++) {
            cnt[s_idx[2 * cj]]++;
            fm |= 1u << s_idx[2 * cj + 1];
        }
        for (int j = 0; j < 16; j++) s_cnt[j] = cnt[j];
        s_fmask = fm;
    }
    __syncthreads();

    if (b == 0) {                               // publish schedule state
        __shared__ int s_n;
        __shared__ int s_live[NSEQ];
        if (tid == 0) { s_n = 0; g_ctr_fwd = 0; g_ctr_inv = 0; }
        if (tid < 64) g_idx[tid] = s_idx[tid];
        __syncthreads();
        if (s_cnt[(tid >> 2) & 15] > 0) {
            int p = atomicAdd(&s_n, 1);
            s_live[p] = tid;
        }
        __syncthreads();
        if (tid == 0) g_nlive = s_n;
        for (int i = tid; i < s_n; i += 512) g_live[i] = s_live[i];
    }

    const int row = b >> 3;
    if (!(s_fmask >> row & 1)) return;          // filter row never referenced

    const float* f = (row < 24) ? (psi + (size_t)row * N_FFT * 2) : phi;
    float2* dst = g_filtrev + (size_t)row * N_FFT;
    const int s0 = (b & 7) * (N_FFT / 8);
#pragma unroll
    for (int k = 0; k < N_FFT / 8 / 512; k++) {
        int s = s0 + tid + k * 512;             // contiguous source (coalesced)
        dst[digitrev4(s)] = make_float2(f[2 * s], f[2 * s + 1]);
    }
}

// Persistent forward: 148 CTAs pull live seqs off a counter.
// [gmem reflect-read + stages 0,1] -> ph<2> -> ph<4> -> [stage 6 + store].
__global__ void __launch_bounds__(NT)
fwd_fft_kernel(const float* __restrict__ x) {
    extern __shared__ float2 sm[];
    __shared__ int s_item;
    const int tid = threadIdx.x;
    const int nlive = g_nlive;
    for (;;) {
        if (tid == 0) s_item = atomicAdd(&g_ctr_fwd, 1);
        __syncthreads();                        // also fences prev-iter smem use
        if (s_item >= nlive) return;
        const int seq = g_live[s_item];
        const float2* xi = (const float2*)(x + (size_t)seq * T_LEN * 2);
        {
            const int v = tid;
            float2 d[4][4];
#pragma unroll
            for (int m = 0; m < 4; m++) {
                int g0 = v + m * 1024;
                d[m][0] = xi[g0];
                d[m][1] = xi[g0 + 4096];
                d[m][2] = xi[8191 - g0];        // reflected half
                d[m][3] = xi[4095 - g0];
            }
#pragma unroll
            for (int m = 0; m < 4; m++)
                bfly4_dif(d[m][0], d[m][1], d[m][2], d[m][3], g_tw[v + m * 1024]);
            {
                float2 w1 = g_tw[v << 2];
                float2 w2 = cmul(w1, w1);
                float2 w3 = cmul(w2, w1);
#pragma unroll
                for (int q = 0; q < 4; q++)
                    bfly4_dif_t(d[0][q], d[1][q], d[2][q], d[3][q], w1, w2, w3);
            }
#pragma unroll
            for (int m = 0; m < 4; m++)
#pragma unroll
                for (int q = 0; q < 4; q++)
                    sm[P(v + m * 1024 + q * 4096)] = d[m][q];
        }
        __syncthreads();

        fwd_fused_phase<2>(sm, tid);
        fwd_fused_phase<4>(sm, tid);

        float4* out4 = (float4*)(g_xhat + (size_t)seq * N_FFT);
#pragma unroll
        for (int k = 0; k < 4; k++) {
            int base = 4 * (tid + k * NT);
            float2 a0 = sm[P(base)],     a1 = sm[P(base + 1)];
            float2 a2 = sm[P(base + 2)], a3 = sm[P(base + 3)];
            bfly4_dif_nw(a0, a1, a2, a3);
            out4[base >> 1]       = make_float4(a0.x, a0.y, a1.x, a1.y);
            out4[(base >> 1) + 1] = make_float4(a2.x, a2.y, a3.x, a3.y);
        }
    }
}

// Persistent inverse: 148 CTAs pull rows [0,1024) off a counter.
// [gmem gather*filter + stage 6] -> ph<4> -> ph<2> ->
// [stages 1,0 fused with unpad + scaled store].
__global__ void __launch_bounds__(NT)
inv_fft_kernel(float* __restrict__ out) {
    extern __shared__ float2 sm[];
    __shared__ int s_item;
    const int tid = threadIdx.x;
    for (;;) {
        if (tid == 0) s_item = atomicAdd(&g_ctr_inv, 1);
        __syncthreads();
        const int b = s_item;
        if (b >= 1024) return;
        const int a  = b & 3;
        const int cj = (b >> 2) & 31;
        const int c  = b >> 7;
        const int jr = g_idx[2 * cj];
        const int f  = g_idx[2 * cj + 1];
        const int src = (c * 16 + jr) * 4 + a;

        const float4* xh4 = (const float4*)(g_xhat + (size_t)src * N_FFT);
        const float4* fr4 = (const float4*)(g_filtrev + (size_t)f * N_FFT);
#pragma unroll
        for (int k = 0; k < 4; k++) {
            int base = 4 * (tid + k * NT);
            float4 xa = xh4[base >> 1], xb = xh4[(base >> 1) + 1];
            float4 fa = fr4[base >> 1], fb = fr4[(base >> 1) + 1];
            float2 a0 = cmul(make_float2(xa.x, xa.y), make_float2(fa.x, fa.y));
            float2 a1 = cmul(make_float2(xa.z, xa.w), make_float2(fa.z, fa.w));
            float2 a2 = cmul(make_float2(xb.x, xb.y), make_float2(fb.x, fb.y));
            float2 a3 = cmul(make_float2(xb.z, xb.w), make_float2(fb.z, fb.w));
            bfly4_dit_nw(a0, a1, a2, a3);
            sm[P(base)] = a0;     sm[P(base + 1)] = a1;
            sm[P(base + 2)] = a2; sm[P(base + 3)] = a3;
        }
        __syncthreads();

        inv_fused_phase<4>(sm, tid);            // stages 5,4
        inv_fused_phase<2>(sm, tid);            // stages 3,2

        // stages 1,0 fused with unpad + scaled store (keep q=0,1 only)
        {
            const int j0 = tid;
            float2 d[4][4];
#pragma unroll
            for (int m = 0; m < 4; m++)
#pragma unroll
                for (int q = 0; q < 4; q++)
                    d[m][q] = sm[P(j0 + m * 1024 + q * 4096)];
            {
                float2 w1 = g_tw[j0 << 2];
                w1.y = -w1.y;
                float2 w2 = cmul(w1, w1);
                float2 w3 = cmul(w2, w1);
#pragma unroll
                for (int q = 0; q < 4; q++)
                    bfly4_dit_t(d[0][q], d[1][q], d[2][q], d[3][q], w1, w2, w3);
            }
            float2* o = (float2*)(out + (size_t)b * T_LEN * 2);
            const float scale = 1.0f / (float)N_FFT;
#pragma unroll
            for (int m = 0; m < 4; m++) {
                float2 w1 = g_tw[j0 + m * 1024];
                w1.y = -w1.y;
                float2 w2 = cmul(w1, w1);
                float2 w3 = cmul(w2, w1);
                float2 b1 = cmul(d[m][1], w1);
                float2 b2 = cmul(d[m][2], w2);
                float2 b3 = cmul(d[m][3], w3);
                float2 t0 = make_float2(d[m][0].x + b2.x, d[m][0].y + b2.y);
                float2 t1 = make_float2(d[m][0].x - b2.x, d[m][0].y - b2.y);
                float2 t2 = make_float2(b1.x + b3.x, b1.y + b3.y);
                float2 t3 = make_float2(b1.x - b3.x, b1.y - b3.y);
                float2 x0 = make_float2(t0.x + t2.x, t0.y + t2.y);        // q=0
                float2 x1 = make_float2(t1.x - t3.y, t1.y + t3.x);        // q=1
                o[j0 + m * 1024]        = make_float2(x0.x * scale, x0.y * scale);
                o[j0 + m * 1024 + 4096] = make_float2(x1.x * scale, x1.y * scale);
            }
        }
        __syncthreads();                        // smem reads done before reuse
    }
}

extern "C" void kernel_launch(void* const* d_in, const int* in_sizes, int n_in,
                              void* d_out, int out_size) {
    const float* x   = (const float*)d_in[0];
    const float* psi = (const float*)d_in[1];
    const float* phi = (const float*)d_in[2];
    const int* idxr  = (const int*)d_in[3];
    float* out       = (float*)d_out;

    cudaFuncSetAttribute(fwd_fft_kernel,
                         cudaFuncAttributeMaxDynamicSharedMemorySize, SMEM_BYTES);
    cudaFuncSetAttribute(inv_fft_kernel,
                         cudaFuncAttributeMaxDynamicSharedMemorySize, SMEM_BYTES);

    prep_kernel<<<216, 512>>>(psi, phi, idxr);
    fwd_fft_kernel<<<NGRID, NT, SMEM_BYTES>>>(x);
    inv_fft_kernel<<<NGRID, NT, SMEM_BYTES>>>(out);
}

// round 17
// speedup vs baseline: 1.0430x; 1.0430x over previous
#include <cuda_runtime.h>

// Shapes: x [8,16,4,8192,2] f32; psi_hat [24,16384,2]; phi_hat [1,16384,2];
// idx [32,2] int32 (sniffed, tolerates int64); out [8,32,4,8192,2] f32.
#define N_FFT    16384
#define T_LEN    8192
#define NT       1024
#define NSEQ     512
#define NGRID    148
// Bank-conflict-avoiding padded smem index: one extra float2 per 16.
#define P(i) ((i) + ((i) >> 4))
#define SMEM_F2    (N_FFT + N_FFT / 16)
#define SMEM_BYTES (SMEM_F2 * 8)             // 139264 bytes

// Named barrier over a 4-warp group (128 threads). Ids 1..8 (id 0 is the
// __syncthreads barrier; mixing counts on one physical barrier is UB).
#define GROUP_BAR(tid) \
    asm volatile("bar.sync %0, %1;" :: "r"(((tid) >> 7) + 1), "r"(128) : "memory")

__device__ __align__(16) float2 g_tw[N_FFT / 4];         // 32KB, L1-hot
__device__ __align__(16) float2 g_xhat[NSEQ * N_FFT];    // 64 MiB
__device__ __align__(16) float2 g_filtrev[26 * N_FFT];   // digit-reversed filters
__device__ int g_idx[64];        // normalized (jr, f) pairs
__device__ int g_live[NSEQ];     // compacted list of referenced fwd seqs
__device__ int g_nlive;
__device__ int g_ctr_fwd;        // persistent-CTA work counters (reset in prep)
__device__ int g_ctr_inv;

__device__ __forceinline__ float2 cmul(float2 a, float2 b) {
    return make_float2(fmaf(a.x, b.x, -a.y * b.y), fmaf(a.x, b.y, a.y * b.x));
}

// DIF butterfly, twiddles applied to outputs.
__device__ __forceinline__ void bfly4_dif_t(float2& x0, float2& x1, float2& x2,
                                            float2& x3, float2 w1, float2 w2, float2 w3) {
    float2 t0 = make_float2(x0.x + x2.x, x0.y + x2.y);
    float2 t1 = make_float2(x0.x - x2.x, x0.y - x2.y);
    float2 t2 = make_float2(x1.x + x3.x, x1.y + x3.y);
    float2 t3 = make_float2(x1.x - x3.x, x1.y - x3.y);
    x0 = make_float2(t0.x + t2.x, t0.y + t2.y);
    float2 y1 = make_float2(t1.x + t3.y, t1.y - t3.x);   // t1 - i*t3
    float2 y2 = make_float2(t0.x - t2.x, t0.y - t2.y);
    float2 y3 = make_float2(t1.x - t3.y, t1.y + t3.x);   // t1 + i*t3
    x1 = cmul(y1, w1);
    x2 = cmul(y2, w2);
    x3 = cmul(y3, w3);
}
__device__ __forceinline__ void bfly4_dif(float2& x0, float2& x1, float2& x2,
                                          float2& x3, float2 w1) {
    float2 w2 = cmul(w1, w1);
    bfly4_dif_t(x0, x1, x2, x3, w1, w2, cmul(w2, w1));
}
__device__ __forceinline__ void bfly4_dif_nw(float2& x0, float2& x1,
                                             float2& x2, float2& x3) {
    float2 t0 = make_float2(x0.x + x2.x, x0.y + x2.y);
    float2 t1 = make_float2(x0.x - x2.x, x0.y - x2.y);
    float2 t2 = make_float2(x1.x + x3.x, x1.y + x3.y);
    float2 t3 = make_float2(x1.x - x3.x, x1.y - x3.y);
    x0 = make_float2(t0.x + t2.x, t0.y + t2.y);
    x1 = make_float2(t1.x + t3.y, t1.y - t3.x);
    x2 = make_float2(t0.x - t2.x, t0.y - t2.y);
    x3 = make_float2(t1.x - t3.y, t1.y + t3.x);
}

// DIT butterfly, conjugated twiddles applied to inputs.
__device__ __forceinline__ void bfly4_dit_t(float2& x0, float2& x1, float2& x2,
                                            float2& x3, float2 w1, float2 w2, float2 w3) {
    float2 b1 = cmul(x1, w1);
    float2 b2 = cmul(x2, w2);
    float2 b3 = cmul(x3, w3);
    float2 t0 = make_float2(x0.x + b2.x, x0.y + b2.y);
    float2 t1 = make_float2(x0.x - b2.x, x0.y - b2.y);
    float2 t2 = make_float2(b1.x + b3.x, b1.y + b3.y);
    float2 t3 = make_float2(b1.x - b3.x, b1.y - b3.y);
    x0 = make_float2(t0.x + t2.x, t0.y + t2.y);
    x1 = make_float2(t1.x - t3.y, t1.y + t3.x);          // t1 + i*t3
    x2 = make_float2(t0.x - t2.x, t0.y - t2.y);
    x3 = make_float2(t1.x + t3.y, t1.y - t3.x);          // t1 - i*t3
}
__device__ __forceinline__ void bfly4_dit(float2& x0, float2& x1, float2& x2,
                                          float2& x3, float2 w1c) {
    float2 w2 = cmul(w1c, w1c);
    bfly4_dit_t(x0, x1, x2, x3, w1c, w2, cmul(w2, w1c));
}
__device__ __forceinline__ void bfly4_dit_nw(float2& x0, float2& x1,
                                             float2& x2, float2& x3) {
    float2 t0 = make_float2(x0.x + x2.x, x0.y + x2.y);
    float2 t1 = make_float2(x0.x - x2.x, x0.y - x2.y);
    float2 t2 = make_float2(x1.x + x3.x, x1.y + x3.y);
    float2 t3 = make_float2(x1.x - x3.x, x1.y - x3.y);
    x0 = make_float2(t0.x + t2.x, t0.y + t2.y);
    x1 = make_float2(t1.x - t3.y, t1.y + t3.x);
    x2 = make_float2(t0.x - t2.x, t0.y - t2.y);
    x3 = make_float2(t1.x + t3.y, t1.y - t3.x);
}

// Fused DIF stage pair (S, S+1), one 16-point unit per thread, smem->smem.
// NOTE: no trailing sync — caller chooses barrier scope.
template <int S>
__device__ __forceinline__ void fwd_fused_phase(float2* sm, int v) {
    constexpr int l2 = 12 - 2 * S;
    constexpr int L  = 1 << l2;
    constexpr int L4 = L >> 2;
    int block = v >> (l2 - 2);
    int j0 = v & (L4 - 1);
    int base = (block << (l2 + 2)) + j0;
    float2 d[4][4];
#pragma unroll
    for (int m = 0; m < 4; m++)
#pragma unroll
        for (int q = 0; q < 4; q++)
            d[m][q] = sm[P(base + m * L4 + q * L)];
#pragma unroll
    for (int m = 0; m < 4; m++)
        bfly4_dif(d[m][0], d[m][1], d[m][2], d[m][3],
                  g_tw[(j0 + m * L4) << (2 * S)]);
    {
        float2 w1 = g_tw[j0 << (2 * S + 2)];
        float2 w2 = cmul(w1, w1);
        float2 w3 = cmul(w2, w1);
#pragma unroll
        for (int q = 0; q < 4; q++)
            bfly4_dif_t(d[0][q], d[1][q], d[2][q], d[3][q], w1, w2, w3);
    }
#pragma unroll
    for (int m = 0; m < 4; m++)
#pragma unroll
        for (int q = 0; q < 4; q++)
            sm[P(base + m * L4 + q * L)] = d[m][q];
}

// Exact inverse: stage S+1 then S, conjugated twiddles. No trailing sync.
template <int S>
__device__ __forceinline__ void inv_fused_phase(float2* sm, int v) {
    constexpr int l2 = 12 - 2 * S;
    constexpr int L  = 1 << l2;
    constexpr int L4 = L >> 2;
    int block = v >> (l2 - 2);
    int j0 = v & (L4 - 1);
    int base = (block << (l2 + 2)) + j0;
    float2 d[4][4];
#pragma unroll
    for (int m = 0; m < 4; m++)
#pragma unroll
        for (int q = 0; q < 4; q++)
            d[m][q] = sm[P(base + m * L4 + q * L)];
    {
        float2 w1 = g_tw[j0 << (2 * S + 2)];
        w1.y = -w1.y;
        float2 w2 = cmul(w1, w1);
        float2 w3 = cmul(w2, w1);
#pragma unroll
        for (int q = 0; q < 4; q++)
            bfly4_dit_t(d[0][q], d[1][q], d[2][q], d[3][q], w1, w2, w3);
    }
#pragma unroll
    for (int m = 0; m < 4; m++) {
        float2 w1 = g_tw[(j0 + m * L4) << (2 * S)];
        w1.y = -w1.y;
        bfly4_dit(d[m][0], d[m][1], d[m][2], d[m][3], w1);
    }
#pragma unroll
    for (int m = 0; m < 4; m++)
#pragma unroll
        for (int q = 0; q < 4; q++)
            sm[P(base + m * L4 + q * L)] = d[m][q];
}

__device__ __forceinline__ int digitrev4(int v) {
    int r = 0;
#pragma unroll
    for (int i = 0; i < 7; i++) { r = (r << 2) | (v & 3); v >>= 2; }
    return r;
}

// Merged prep kernel (unchanged from R16), grid = 216 x 512.
__global__ void prep_kernel(const float* __restrict__ psi,
                            const float* __restrict__ phi,
                            const int* __restrict__ raw) {
    const int b   = blockIdx.x;
    const int tid = threadIdx.x;

    if (b >= 208) {                             // twiddle chunk
        int k = (b - 208) * 512 + tid;
        double s, c;
        sincospi(-2.0 * (double)k / (double)N_FFT, &s, &c);
        g_tw[k] = make_float2((float)c, (float)s);
        return;
    }

    __shared__ int s_idx[64];
    __shared__ int s_cnt[16];
    __shared__ unsigned s_fmask;
    if (tid < 32) {
        int odd = raw[2 * tid + 1];
        unsigned nz = __ballot_sync(0xffffffffu, odd != 0);
        int jr, f;
        if (nz) { jr = raw[2 * tid];     f = raw[2 * tid + 1]; }  // int32
        else    { jr = raw[4 * tid];     f = raw[4 * tid + 2]; }  // int64 low words
        s_idx[2 * tid]     = min(max(jr, 0), 15);
        s_idx[2 * tid + 1] = min(max(f, 0), 25);
    }
    __syncthreads();
    if (tid == 0) {
        int cnt[16];
        unsigned fm = 0;
        for (int j = 0; j < 16; j++) cnt[j] = 0;
        for (int cj = 0; cj < 32; cj++) {
            cnt[s_idx[2 * cj]]++;
            fm |= 1u << s_idx[2 * cj + 1];
        }
        for (int j = 0; j < 16; j++) s_cnt[j] = cnt[j];
        s_fmask = fm;
    }
    __syncthreads();

    if (b == 0) {
        __shared__ int s_n;
        __shared__ int s_live[NSEQ];
        if (tid == 0) { s_n = 0; g_ctr_fwd = 0; g_ctr_inv = 0; }
        if (tid < 64) g_idx[tid] = s_idx[tid];
        __syncthreads();
        if (s_cnt[(tid >> 2) & 15] > 0) {
            int p = atomicAdd(&s_n, 1);
            s_live[p] = tid;
        }
        __syncthreads();
        if (tid == 0) g_nlive = s_n;
        for (int i = tid; i < s_n; i += 512) g_live[i] = s_live[i];
    }

    const int row = b >> 3;
    if (!(s_fmask >> row & 1)) return;

    const float* f = (row < 24) ? (psi + (size_t)row * N_FFT * 2) : phi;
    float2* dst = g_filtrev + (size_t)row * N_FFT;
    const int s0 = (b & 7) * (N_FFT / 8);
#pragma unroll
    for (int k = 0; k < N_FFT / 8 / 512; k++) {
        int s = s0 + tid + k * 512;             // contiguous source (coalesced)
        dst[digitrev4(s)] = make_float2(f[2 * s], f[2 * s + 1]);
    }
}

// Persistent forward. Barriers: full after init (scattered writes);
// 4-warp group bar after ph<2> (1024-block = warp-pair locality);
// __syncwarp before final stage (512-span warp locality).
__global__ void __launch_bounds__(NT)
fwd_fft_kernel(const float* __restrict__ x) {
    extern __shared__ float2 sm[];
    __shared__ int s_item;
    const int tid = threadIdx.x;
    const int lane = tid & 31;
    const int w    = tid >> 5;
    const int nlive = g_nlive;
    for (;;) {
        if (tid == 0) s_item = atomicAdd(&g_ctr_fwd, 1);
        __syncthreads();                        // broadcast + fence prev item
        if (s_item >= nlive) return;
        const int seq = g_live[s_item];
        const float2* xi = (const float2*)(x + (size_t)seq * T_LEN * 2);
        {
            const int v = tid;
            float2 d[4][4];
#pragma unroll
            for (int m = 0; m < 4; m++) {
                int g0 = v + m * 1024;
                d[m][0] = xi[g0];
                d[m][1] = xi[g0 + 4096];
                d[m][2] = xi[8191 - g0];        // reflected half
                d[m][3] = xi[4095 - g0];
            }
#pragma unroll
            for (int m = 0; m < 4; m++)
                bfly4_dif(d[m][0], d[m][1], d[m][2], d[m][3], g_tw[v + m * 1024]);
            {
                float2 w1 = g_tw[v << 2];
                float2 w2 = cmul(w1, w1);
                float2 w3 = cmul(w2, w1);
#pragma unroll
                for (int q = 0; q < 4; q++)
                    bfly4_dif_t(d[0][q], d[1][q], d[2][q], d[3][q], w1, w2, w3);
            }
#pragma unroll
            for (int m = 0; m < 4; m++)
#pragma unroll
                for (int q = 0; q < 4; q++)
                    sm[P(v + m * 1024 + q * 4096)] = d[m][q];
        }
        __syncthreads();

        fwd_fused_phase<2>(sm, tid);            // touches 1024-block tid>>6
        GROUP_BAR(tid);                         // 4-warp group covers the pair
        fwd_fused_phase<4>(sm, tid);            // touches 512-span of warp w
        __syncwarp();

        // final stage 6 + store; chunks warp-local: c = 512w + 128k + 4*lane
        float4* out4 = (float4*)(g_xhat + (size_t)seq * N_FFT);
#pragma unroll
        for (int k = 0; k < 4; k++) {
            int c = 512 * w + 128 * k + 4 * lane;
            float2 a0 = sm[P(c)],     a1 = sm[P(c + 1)];
            float2 a2 = sm[P(c + 2)], a3 = sm[P(c + 3)];
            bfly4_dif_nw(a0, a1, a2, a3);
            out4[c >> 1]       = make_float4(a0.x, a0.y, a1.x, a1.y);
            out4[(c >> 1) + 1] = make_float4(a2.x, a2.y, a3.x, a3.y);
        }
    }
}

// Persistent inverse (mirror): warp-local gmem load + stage 6 -> syncwarp ->
// ph<4> -> group bar -> ph<2> -> full bar -> ph<0> fused with unpad + store.
__global__ void __launch_bounds__(NT)
inv_fft_kernel(float* __restrict__ out) {
    extern __shared__ float2 sm[];
    __shared__ int s_item;
    const int tid = threadIdx.x;
    const int lane = tid & 31;
    const int w    = tid >> 5;
    for (;;) {
        if (tid == 0) s_item = atomicAdd(&g_ctr_inv, 1);
        __syncthreads();
        const int b = s_item;
        if (b >= 1024) return;
        const int a  = b & 3;
        const int cj = (b >> 2) & 31;
        const int c8 = b >> 7;
        const int jr = g_idx[2 * cj];
        const int f  = g_idx[2 * cj + 1];
        const int src = (c8 * 16 + jr) * 4 + a;

        const float4* xh4 = (const float4*)(g_xhat + (size_t)src * N_FFT);
        const float4* fr4 = (const float4*)(g_filtrev + (size_t)f * N_FFT);
#pragma unroll
        for (int k = 0; k < 4; k++) {
            int c = 512 * w + 128 * k + 4 * lane;   // warp-local chunk
            float4 xa = xh4[c >> 1], xb = xh4[(c >> 1) + 1];
            float4 fa = fr4[c >> 1], fb = fr4[(c >> 1) + 1];
            float2 a0 = cmul(make_float2(xa.x, xa.y), make_float2(fa.x, fa.y));
            float2 a1 = cmul(make_float2(xa.z, xa.w), make_float2(fa.z, fa.w));
            float2 a2 = cmul(make_float2(xb.x, xb.y), make_float2(fb.x, fb.y));
            float2 a3 = cmul(make_float2(xb.z, xb.w), make_float2(fb.z, fb.w));
            bfly4_dit_nw(a0, a1, a2, a3);
            sm[P(c)] = a0;     sm[P(c + 1)] = a1;
            sm[P(c + 2)] = a2; sm[P(c + 3)] = a3;
        }
        __syncwarp();                           // 512-span is warp-local

        inv_fused_phase<4>(sm, tid);            // stages 5,4 (512-span)
        GROUP_BAR(tid);                         // pair locality for ph<2>
        inv_fused_phase<2>(sm, tid);            // stages 3,2 (1024-block)
        __syncthreads();                        // ph<0> reads everything

        // stages 1,0 fused with unpad + scaled store (keep q=0,1 only)
        {
            const int j0 = tid;
            float2 d[4][4];
#pragma unroll
            for (int m = 0; m < 4; m++)
#pragma unroll
                for (int q = 0; q < 4; q++)
                    d[m][q] = sm[P(j0 + m * 1024 + q * 4096)];
            {
                float2 w1 = g_tw[j0 << 2];
                w1.y = -w1.y;
                float2 w2 = cmul(w1, w1);
                float2 w3 = cmul(w2, w1);
#pragma unroll
                for (int q = 0; q < 4; q++)
                    bfly4_dit_t(d[0][q], d[1][q], d[2][q], d[3][q], w1, w2, w3);
            }
            float2* o = (float2*)(out + (size_t)b * T_LEN * 2);
            const float scale = 1.0f / (float)N_FFT;
#pragma unroll
            for (int m = 0; m < 4; m++) {
                float2 w1 = g_tw[j0 + m * 1024];
                w1.y = -w1.y;
                float2 w2 = cmul(w1, w1);
                float2 w3 = cmul(w2, w1);
                float2 b1 = cmul(d[m][1], w1);
                float2 b2 = cmul(d[m][2], w2);
                float2 b3 = cmul(d[m][3], w3);
                float2 t0 = make_float2(d[m][0].x + b2.x, d[m][0].y + b2.y);
                float2 t1 = make_float2(d[m][0].x - b2.x, d[m][0].y - b2.y);
                float2 t2 = make_float2(b1.x + b3.x, b1.y + b3.y);
                float2 t3 = make_float2(b1.x - b3.x, b1.y - b3.y);
                float2 x0 = make_float2(t0.x + t2.x, t0.y + t2.y);        // q=0
                float2 x1 = make_float2(t1.x - t3.y, t1.y + t3.x);        // q=1
                o[j0 + m * 1024]        = make_float2(x0.x * scale, x0.y * scale);
                o[j0 + m * 1024 + 4096] = make_float2(x1.x * scale, x1.y * scale);
            }
        }
    }
}

extern "C" void kernel_launch(void* const* d_in, const int* in_sizes, int n_in,
                              void* d_out, int out_size) {
    const float* x   = (const float*)d_in[0];
    const float* psi = (const float*)d_in[1];
    const float* phi = (const float*)d_in[2];
    const int* idxr  = (const int*)d_in[3];
    float* out       = (float*)d_out;

    cudaFuncSetAttribute(fwd_fft_kernel,
                         cudaFuncAttributeMaxDynamicSharedMemorySize, SMEM_BYTES);
    cudaFuncSetAttribute(inv_fft_kernel,
                         cudaFuncAttributeMaxDynamicSharedMemorySize, SMEM_BYTES);

    prep_kernel<<<216, 512>>>(psi, phi, idxr);
    fwd_fft_kernel<<<NGRID, NT, SMEM_BYTES>>>(x);
    inv_fft_kernel<<<NGRID, NT, SMEM_BYTES>>>(out);
}